// round 9
// baseline (speedup 1.0000x reference)
#include <cuda_runtime.h>
#include <cuda_bf16.h>
#include <cstdint>

#define MAXN 50000
#define MAXE 800000
#define Hd   64
#define MAXK 16
#define NTGT (2 + MAXK)
#define NBLK 128
#define NTHR 256

// ---------------- device scratch (no allocs allowed) ----------------
static __device__ float    g_agg1[(size_t)MAXN * Hd]; // layer-1 agg (S1 rows only)
static __device__ float    g_h1[(size_t)MAXN * Hd];   // relu(conv1 out) (S1 rows only)
static __device__ int      g_is64;
static __device__ int      g_targets[NTGT];           // [curr, dest, nbr0..15]
static __device__ unsigned g_bitmap[(MAXN + 31) / 32];// membership of S1
static __device__ int      g_s1[MAXN];                // S1 node list
static __device__ int      g_ns1;
static __device__ int      g_elist2[MAXE];            // edges with dst in targets
static __device__ int      g_ne2;

// grid barrier state (count self-resets each barrier; gen monotonic)
static __device__ volatile unsigned g_gen;
static __device__ unsigned g_count;

__device__ __forceinline__ void grid_barrier() {
    __syncthreads();
    if (threadIdx.x == 0) {
        __threadfence();
        unsigned old = g_gen;
        if (atomicAdd(&g_count, 1) + 1 == gridDim.x) {
            g_count = 0;
            __threadfence();
            atomicAdd((unsigned*)&g_count + 0, 0); // no-op ordering aid
            atomicAdd((unsigned*)&g_gen, 1);
        } else {
            while (g_gen == old) __nanosleep(32);
        }
        __threadfence();
    }
    __syncthreads();
}

// zero one agg1 row (done by the thread that first inserts the node into S1)
__device__ __forceinline__ void zero_agg1_row(int node) {
    float4* p = (float4*)(g_agg1 + (size_t)node * Hd);
    #pragma unroll
    for (int i = 0; i < 16; i++) p[i] = make_float4(0.f, 0.f, 0.f, 0.f);
}

// ---------------- the whole problem in one persistent kernel ----------------
__global__ void __launch_bounds__(NTHR) k_mono(
        const float* __restrict__ x, const void* __restrict__ ei,
        const void* __restrict__ curr, const void* __restrict__ dest,
        const void* __restrict__ nbr, const float* __restrict__ ea,
        const float* __restrict__ We1, const float* __restrict__ be1,
        const float* __restrict__ W1a, const float* __restrict__ b1a,
        const float* __restrict__ W1b, const float* __restrict__ b1b,
        const float* __restrict__ We2, const float* __restrict__ be2,
        const float* __restrict__ W2a, const float* __restrict__ b2a,
        const float* __restrict__ W2b, const float* __restrict__ b2b,
        const float* __restrict__ Wl1, const float* __restrict__ bl1,
        const float* __restrict__ Wl2, const float* __restrict__ bl2,
        float* __restrict__ out, int E, long long N, int K) {
    __shared__ __align__(16) float sIn[4 * Hd];
    __shared__ __align__(16) float sMu[4 * Hd];
    __shared__ __align__(16) float w[Hd];
    __shared__ __align__(16) float b[Hd];
    __shared__ __align__(16) float cd[Hd];
    __shared__ __align__(16) float sA[NTGT * Hd];
    __shared__ __align__(16) float sU[NTGT * Hd];
    __shared__ __align__(16) float sH2[NTGT * Hd];
    __shared__ __align__(16) float sZ[MAXK * Hd];
    __shared__ int tg[NTGT];

    int tid  = threadIdx.x;
    int bid  = blockIdx.x;
    int lane = tid & 31;
    int B    = gridDim.x;

    // ---------------- phase 0: prep (block 0 only) ----------------
    if (bid == 0) {
        if (tid == 0) {
            const long long* p = (const long long*)ei;
            int n = E < 8 ? E : 8;
            int ok = 1;
            for (int q = 0; q < n; q++) {
                long long v = p[q];
                if (v < 0 || v >= N) { ok = 0; break; }
            }
            g_is64 = ok;
            g_ne2 = 0; g_ns1 = 0;
        }
        __syncthreads();
        int is64 = g_is64;
        for (int i = tid; i < (MAXN + 31) / 32; i += NTHR) g_bitmap[i] = 0u;
        if (tid < NTGT) {
            int v = -1;
            if (tid == 0)      v = is64 ? (int)((const long long*)curr)[0] : ((const int*)curr)[0];
            else if (tid == 1) v = is64 ? (int)((const long long*)dest)[0] : ((const int*)dest)[0];
            else if (tid < 2 + K)
                v = is64 ? (int)((const long long*)nbr)[tid - 2] : ((const int*)nbr)[tid - 2];
            g_targets[tid] = v;
        }
        __syncthreads();
        if (tid < 2 + K) {
            int v = g_targets[tid];
            unsigned bit = 1u << (v & 31);
            unsigned old = atomicOr(&g_bitmap[v >> 5], bit);
            if (!(old & bit)) {
                int sl = atomicAdd(&g_ns1, 1);
                g_s1[sl] = v;
                zero_agg1_row(v);
            }
        }
    }
    grid_barrier();

    int is64 = g_is64;
    if (tid < NTGT) tg[tid] = g_targets[tid];
    __syncthreads();

    // ---------------- phase A: scan dst for target hits; grow S1 ----------------
    {
        int gwarp  = (bid * NTHR + tid) >> 5;
        int nwarps = (B * NTHR) >> 5;
        for (int wb = gwarp * 128; wb < E; wb += nwarps * 128) {
            int base = wb + lane * 4;
            int dv[4];
            if (base + 4 <= E) {
                if (is64) {
                    const long long* p = (const long long*)ei + E + base;
                    longlong2 a = *(const longlong2*)p;
                    longlong2 c = *(const longlong2*)(p + 2);
                    dv[0] = (int)a.x; dv[1] = (int)a.y; dv[2] = (int)c.x; dv[3] = (int)c.y;
                } else {
                    int4 a = *(const int4*)((const int*)ei + E + base);
                    dv[0] = a.x; dv[1] = a.y; dv[2] = a.z; dv[3] = a.w;
                }
            } else {
                for (int j = 0; j < 4; j++)
                    dv[j] = (base + j < E)
                          ? (is64 ? (int)((const long long*)ei)[E + base + j]
                                  : ((const int*)ei)[E + base + j])
                          : -1;
            }
            #pragma unroll
            for (int j = 0; j < 4; j++) {
                int d = dv[j];
                bool match = false;
                #pragma unroll
                for (int t = 0; t < NTGT; t++) match |= (d == tg[t]);
                if (!match) continue;
                int e = base + j;
                int pos = atomicAdd(&g_ne2, 1);
                g_elist2[pos] = e;
                int s = is64 ? (int)((const long long*)ei)[e] : ((const int*)ei)[e];
                unsigned bit = 1u << (s & 31);
                unsigned old = atomicOr(&g_bitmap[s >> 5], bit);
                if (!(old & bit)) {
                    int sl = atomicAdd(&g_ns1, 1);
                    g_s1[sl] = s;
                    zero_agg1_row(s);
                }
            }
        }
    }
    grid_barrier();

    // ---------------- phase B: scan dst for S1 hits; edge pass 1 inline ---------
    {
        float2 wv = *((const float2*)We1 + lane);
        float2 bv = *((const float2*)be1 + lane);
        int gwarp  = (bid * NTHR + tid) >> 5;
        int nwarps = (B * NTHR) >> 5;
        for (int wb = gwarp * 128; wb < E; wb += nwarps * 128) {
            int base = wb + lane * 4;
            int dv[4];
            if (base + 4 <= E) {
                if (is64) {
                    const long long* p = (const long long*)ei + E + base;
                    longlong2 a = *(const longlong2*)p;
                    longlong2 c = *(const longlong2*)(p + 2);
                    dv[0] = (int)a.x; dv[1] = (int)a.y; dv[2] = (int)c.x; dv[3] = (int)c.y;
                } else {
                    int4 a = *(const int4*)((const int*)ei + E + base);
                    dv[0] = a.x; dv[1] = a.y; dv[2] = a.z; dv[3] = a.w;
                }
            } else {
                for (int j = 0; j < 4; j++)
                    dv[j] = (base + j < E)
                          ? (is64 ? (int)((const long long*)ei)[E + base + j]
                                  : ((const int*)ei)[E + base + j])
                          : -1;
            }
            #pragma unroll
            for (int j = 0; j < 4; j++) {
                int d = dv[j];
                bool hit = (d >= 0) && ((g_bitmap[d >> 5] >> (d & 31)) & 1u);
                unsigned m = __ballot_sync(0xffffffffu, hit);
                while (m) {
                    int src_lane = __ffs(m) - 1;
                    m &= m - 1;
                    int e  = __shfl_sync(0xffffffffu, base + j, src_lane);
                    int dd = __shfl_sync(0xffffffffu, d, src_lane);
                    long long s = is64 ? ((const long long*)ei)[e]
                                       : (long long)((const int*)ei)[e];
                    float a = __ldg(&ea[e]);
                    float2 xv = *((const float2*)(x + s * Hd) + lane);
                    float m0 = fmaxf(xv.x + fmaf(a, wv.x, bv.x), 0.f);
                    float m1 = fmaxf(xv.y + fmaf(a, wv.y, bv.y), 0.f);
                    float* dp = g_agg1 + (size_t)dd * Hd + 2 * lane;
                    asm volatile("red.global.add.v2.f32 [%0], {%1,%2};"
                                 :: "l"(dp), "f"(m0), "f"(m1) : "memory");
                }
            }
        }
    }
    grid_barrier();

    // ---------------- phase C: layer-1 MLP at S1 nodes ----------------
    {
        int ns1 = g_ns1;
        int nl  = tid >> 6;
        int j   = tid & 63;
        for (int base = bid * 4; base < ns1; base += B * 4) {
            int idx = base + nl;
            bool valid = (idx < ns1);
            if (valid) {
                size_t node = (size_t)g_s1[idx];
                sIn[tid] = x[node * Hd + j] + g_agg1[node * Hd + j];
            } else sIn[tid] = 0.f;
            __syncthreads();
            {
                float acc = __ldg(&b1a[j]);
                const float* in = &sIn[nl * Hd];
                #pragma unroll 16
                for (int k = 0; k < Hd; k++)
                    acc = fmaf(in[k], __ldg(&W1a[k * Hd + j]), acc);
                sMu[tid] = fmaxf(acc, 0.f);
            }
            __syncthreads();
            {
                float acc = __ldg(&b1b[j]);
                const float* u = &sMu[nl * Hd];
                #pragma unroll 16
                for (int k = 0; k < Hd; k++)
                    acc = fmaf(u[k], __ldg(&W1b[k * Hd + j]), acc);
                if (valid) {
                    size_t node = (size_t)g_s1[idx];
                    g_h1[node * Hd + j] = fmaxf(acc, 0.f);
                }
            }
            __syncthreads();
        }
    }
    grid_barrier();

    // ---------------- phase D: edge pass 2 + layer-2 MLP + Q head (block 0) -----
    if (bid != 0) return;

    int nt = 2 + K;
    if (tid < Hd) { w[tid] = We2[tid]; b[tid] = be2[tid]; }
    for (int i = tid; i < NTGT * Hd; i += NTHR) sA[i] = 0.f;
    __syncthreads();

    int count = g_ne2;
    for (int idx = tid; idx < count * 16; idx += NTHR) {
        int e = g_elist2[idx >> 4];
        int l = idx & 15;
        int d;
        long long s;
        if (is64) {
            s = ((const long long*)ei)[e];
            d = (int)((const long long*)ei)[E + e];
        } else {
            s = (long long)((const int*)ei)[e];
            d = ((const int*)ei)[E + e];
        }
        float a = __ldg(&ea[e]);
        float4 xv = *((const float4*)(g_h1 + s * Hd) + l);
        float4 wv = ((const float4*)w)[l];
        float4 bv = ((const float4*)b)[l];
        float4 m;
        m.x = fmaxf(xv.x + fmaf(a, wv.x, bv.x), 0.f);
        m.y = fmaxf(xv.y + fmaf(a, wv.y, bv.y), 0.f);
        m.z = fmaxf(xv.z + fmaf(a, wv.z, bv.z), 0.f);
        m.w = fmaxf(xv.w + fmaf(a, wv.w, bv.w), 0.f);
        #pragma unroll
        for (int t = 0; t < NTGT; t++) {
            if (d == tg[t]) {
                float* base2 = &sA[t * Hd + l * 4];
                atomicAdd(base2 + 0, m.x);
                atomicAdd(base2 + 1, m.y);
                atomicAdd(base2 + 2, m.z);
                atomicAdd(base2 + 3, m.w);
            }
        }
    }
    __syncthreads();

    for (int i = tid; i < nt * Hd; i += NTHR) {
        int slot = i >> 6, j = i & 63;
        sA[i] += g_h1[(size_t)tg[slot] * Hd + j];
    }
    __syncthreads();

    for (int i = tid; i < nt * Hd; i += NTHR) {
        int slot = i >> 6, j = i & 63;
        float acc = b2a[j];
        const float* t = &sA[slot * Hd];
        #pragma unroll 8
        for (int k = 0; k < Hd; k++) acc = fmaf(t[k], __ldg(&W2a[k * Hd + j]), acc);
        sU[i] = fmaxf(acc, 0.f);
    }
    __syncthreads();

    for (int i = tid; i < nt * Hd; i += NTHR) {
        int slot = i >> 6, j = i & 63;
        float acc = b2b[j];
        const float* u = &sU[slot * Hd];
        #pragma unroll 8
        for (int k = 0; k < Hd; k++) acc = fmaf(u[k], __ldg(&W2b[k * Hd + j]), acc);
        sH2[i] = acc;
    }
    __syncthreads();

    if (tid < Hd) {
        float acc = bl1[tid];
        #pragma unroll 8
        for (int t = 0; t < Hd; t++)
            acc = fmaf(sH2[t], __ldg(&Wl1[t * Hd + tid]), acc);
        #pragma unroll 8
        for (int t = 0; t < Hd; t++)
            acc = fmaf(sH2[Hd + t], __ldg(&Wl1[(Hd + t) * Hd + tid]), acc);
        cd[tid] = acc;
    }
    __syncthreads();

    for (int i = tid; i < K * Hd; i += NTHR) {
        int k = i >> 6, j = i & 63;
        float acc = cd[j];
        const float* nb = &sH2[(2 + k) * Hd];
        #pragma unroll 8
        for (int t = 0; t < Hd; t++)
            acc = fmaf(nb[t], __ldg(&Wl1[(2 * Hd + t) * Hd + j]), acc);
        sZ[i] = fmaxf(acc, 0.f);
    }
    __syncthreads();

    if (tid < K) {
        float acc = bl2[0];
        #pragma unroll 8
        for (int j = 0; j < Hd; j++) acc = fmaf(sZ[tid * Hd + j], Wl2[j], acc);
        out[tid] = acc;
    }
}

// ---------------- launcher ----------------
extern "C" void kernel_launch(void* const* d_in, const int* in_sizes, int n_in,
                              void* d_out, int out_size) {
    const float* x    = (const float*)d_in[0];
    const void*  ei   = d_in[1];
    const void*  curr = d_in[2];
    const void*  dest = d_in[3];
    const void*  nbr  = d_in[4];
    const float* ea   = (const float*)d_in[5];
    const float* We1  = (const float*)d_in[6];
    const float* be1  = (const float*)d_in[7];
    const float* W1a  = (const float*)d_in[8];
    const float* b1a  = (const float*)d_in[9];
    const float* W1b  = (const float*)d_in[10];
    const float* b1b  = (const float*)d_in[11];
    const float* We2  = (const float*)d_in[12];
    const float* be2  = (const float*)d_in[13];
    const float* W2a  = (const float*)d_in[14];
    const float* b2a  = (const float*)d_in[15];
    const float* W2b  = (const float*)d_in[16];
    const float* b2b  = (const float*)d_in[17];
    const float* Wl1  = (const float*)d_in[18];
    const float* bl1  = (const float*)d_in[19];
    const float* Wl2  = (const float*)d_in[20];
    const float* bl2  = (const float*)d_in[21];

    int N = in_sizes[0] / Hd;
    int E = in_sizes[5];
    int K = in_sizes[4];
    if (K > MAXK) K = MAXK;

    k_mono<<<NBLK, NTHR>>>(x, ei, curr, dest, nbr, ea,
                           We1, be1, W1a, b1a, W1b, b1b,
                           We2, be2, W2a, b2a, W2b, b2b,
                           Wl1, bl1, Wl2, bl2,
                           (float*)d_out, E, (long long)N, K);
}

// round 10
// speedup vs baseline: 1.5000x; 1.5000x over previous
#include <cuda_runtime.h>
#include <cuda_bf16.h>
#include <cstdint>

#define MAXN 50000
#define MAXE 800000
#define Hd   64
#define MAXK 16
#define NTGT (2 + MAXK)

// ---------------- device scratch (no allocs allowed) ----------------
// INVARIANT: g_bitmap is all-zero and g_ns1 == g_ne2 == 0 at every
// kernel_launch entry (zero-initialized at load; k_final2 restores it).
static __device__ float    g_agg1[(size_t)MAXN * Hd]; // layer-1 agg (S1 rows only)
static __device__ float    g_h1[(size_t)MAXN * Hd];   // relu(conv1 out) (S1 rows only)
static __device__ int      g_is64;
static __device__ unsigned g_bitmap[(MAXN + 31) / 32];// membership of S1
static __device__ int      g_s1[MAXN];                // S1 node list
static __device__ int      g_ns1;
static __device__ int      g_elist2[MAXE];            // edges with dst in targets
static __device__ int      g_ne2;

__device__ __forceinline__ void zero_agg1_row(int node) {
    float4* p = (float4*)(g_agg1 + (size_t)node * Hd);
    #pragma unroll
    for (int i = 0; i < 16; i++) p[i] = make_float4(0.f, 0.f, 0.f, 0.f);
}

__device__ __forceinline__ int sniff_is64(const void* ei, int E, long long N) {
    const long long* p = (const long long*)ei;
    int n = E < 8 ? E : 8;
    int ok = 1;
    for (int q = 0; q < n; q++) {
        long long v = p[q];
        if (v < 0 || v >= N) { ok = 0; break; }
    }
    return ok;
}

__device__ __forceinline__ int load_idx(const void* p, int i, int is64) {
    return is64 ? (int)((const long long*)p)[i] : ((const int*)p)[i];
}

// ---------------- scan A: edges with dst in targets; build S1 --------------
// Self-contained: every block loads targets + sniffs dtype itself (L2 hits).
__global__ void __launch_bounds__(256) k_scanA(
        const void* __restrict__ ei, const void* __restrict__ curr,
        const void* __restrict__ dest, const void* __restrict__ nbr,
        int E, long long N, int K) {
    __shared__ int tg[NTGT];
    __shared__ int s_is64;
    int tid = threadIdx.x;
    if (tid == 0) {
        int ok = sniff_is64(ei, E, N);
        s_is64 = ok;
        if (blockIdx.x == 0) g_is64 = ok;
    }
    __syncthreads();
    int is64 = s_is64;
    if (tid < NTGT) {
        int v = -1;
        if (tid == 0)      v = load_idx(curr, 0, is64);
        else if (tid == 1) v = load_idx(dest, 0, is64);
        else if (tid < 2 + K) v = load_idx(nbr, tid - 2, is64);
        tg[tid] = v;
    }
    __syncthreads();

    // block 0 seeds S1 with the targets (bitmap dedups vs src inserts below)
    if (blockIdx.x == 0 && tid < 2 + K) {
        int v = tg[tid];
        unsigned bit = 1u << (v & 31);
        unsigned old = atomicOr(&g_bitmap[v >> 5], bit);
        if (!(old & bit)) {
            int sl = atomicAdd(&g_ns1, 1);
            g_s1[sl] = v;
            zero_agg1_row(v);
        }
    }

    int base = (blockIdx.x * 256 + tid) * 4;
    if (base >= E) return;

    int dv[4];
    if (base + 4 <= E) {
        if (is64) {
            const long long* p = (const long long*)ei + E + base;
            longlong2 a = *(const longlong2*)p;
            longlong2 c = *(const longlong2*)(p + 2);
            dv[0] = (int)a.x; dv[1] = (int)a.y; dv[2] = (int)c.x; dv[3] = (int)c.y;
        } else {
            int4 a = *(const int4*)((const int*)ei + E + base);
            dv[0] = a.x; dv[1] = a.y; dv[2] = a.z; dv[3] = a.w;
        }
    } else {
        for (int j = 0; j < 4; j++)
            dv[j] = (base + j < E) ? load_idx(ei, E + base + j, is64) : -1;
    }

    #pragma unroll
    for (int j = 0; j < 4; j++) {
        int d = dv[j];
        bool match = false;
        #pragma unroll
        for (int t = 0; t < NTGT; t++) match |= (d == tg[t]);
        if (!match) continue;
        int e = base + j;
        int pos = atomicAdd(&g_ne2, 1);
        g_elist2[pos] = e;
        int s = load_idx(ei, e, is64);
        unsigned bit = 1u << (s & 31);
        unsigned old = atomicOr(&g_bitmap[s >> 5], bit);
        if (!(old & bit)) {
            int sl = atomicAdd(&g_ns1, 1);
            g_s1[sl] = s;
            zero_agg1_row(s);
        }
    }
}

// ---------------- scan B + edge pass 1, warp-cooperative -------------------
__global__ void __launch_bounds__(256) k_scanB(
        const float* __restrict__ x, const void* __restrict__ ei,
        const float* __restrict__ ea, const float* __restrict__ We1,
        const float* __restrict__ be1, int E) {
    int tid  = threadIdx.x;
    int lane = tid & 31;
    int is64 = g_is64;
    int base = (blockIdx.x * 256 + tid) * 4;

    float2 wv = *((const float2*)We1 + lane);
    float2 bv = *((const float2*)be1 + lane);

    int dv[4];
    if (base < E) {
        if (base + 4 <= E) {
            if (is64) {
                const long long* p = (const long long*)ei + E + base;
                longlong2 a = *(const longlong2*)p;
                longlong2 c = *(const longlong2*)(p + 2);
                dv[0] = (int)a.x; dv[1] = (int)a.y; dv[2] = (int)c.x; dv[3] = (int)c.y;
            } else {
                int4 a = *(const int4*)((const int*)ei + E + base);
                dv[0] = a.x; dv[1] = a.y; dv[2] = a.z; dv[3] = a.w;
            }
        } else {
            for (int j = 0; j < 4; j++)
                dv[j] = (base + j < E) ? load_idx(ei, E + base + j, is64) : -1;
        }
    } else {
        dv[0] = dv[1] = dv[2] = dv[3] = -1;
    }

    #pragma unroll
    for (int j = 0; j < 4; j++) {
        int d = dv[j];
        bool hit = (d >= 0) && ((g_bitmap[d >> 5] >> (d & 31)) & 1u);
        unsigned m = __ballot_sync(0xffffffffu, hit);
        while (m) {
            int src_lane = __ffs(m) - 1;
            m &= m - 1;
            int e  = __shfl_sync(0xffffffffu, base + j, src_lane);
            int dd = __shfl_sync(0xffffffffu, d, src_lane);
            long long s = is64 ? ((const long long*)ei)[e]
                               : (long long)((const int*)ei)[e];
            float a = __ldg(&ea[e]);
            float2 xv = *((const float2*)(x + s * Hd) + lane);
            float m0 = fmaxf(xv.x + fmaf(a, wv.x, bv.x), 0.f);
            float m1 = fmaxf(xv.y + fmaf(a, wv.y, bv.y), 0.f);
            float* dp = g_agg1 + (size_t)dd * Hd + 2 * lane;
            asm volatile("red.global.add.v2.f32 [%0], {%1,%2};"
                         :: "l"(dp), "f"(m0), "f"(m1) : "memory");
        }
    }
}

// ---------------- layer-1 MLP at S1 nodes ----------------------------------
// 4 nodes/block, 160 blocks: ns1 (~320) covered in one iteration.
__global__ void __launch_bounds__(256) k_mlp1v2(
        const float* __restrict__ x,
        const float* __restrict__ Wa, const float* __restrict__ ba,
        const float* __restrict__ Wb, const float* __restrict__ bb) {
    __shared__ __align__(16) float sIn[4 * Hd];
    __shared__ __align__(16) float sU[4 * Hd];

    int tid = threadIdx.x;
    int nl  = tid >> 6;
    int j   = tid & 63;
    int ns1 = g_ns1;

    for (int base = blockIdx.x * 4; base < ns1; base += gridDim.x * 4) {
        int idx = base + nl;
        bool valid = (idx < ns1);

        if (valid) {
            size_t node = (size_t)g_s1[idx];
            sIn[tid] = x[node * Hd + j] + g_agg1[node * Hd + j];
        } else {
            sIn[tid] = 0.f;
        }
        __syncthreads();

        {
            float acc = __ldg(&ba[j]);
            const float* in = &sIn[nl * Hd];
            #pragma unroll 16
            for (int k = 0; k < Hd; k++)
                acc = fmaf(in[k], __ldg(&Wa[k * Hd + j]), acc);
            sU[tid] = fmaxf(acc, 0.f);
        }
        __syncthreads();

        {
            float acc = __ldg(&bb[j]);
            const float* u = &sU[nl * Hd];
            #pragma unroll 16
            for (int k = 0; k < Hd; k++)
                acc = fmaf(u[k], __ldg(&Wb[k * Hd + j]), acc);
            if (valid) {
                size_t node = (size_t)g_s1[idx];
                g_h1[node * Hd + j] = fmaxf(acc, 0.f);
            }
        }
        __syncthreads();
    }
}

// ---------------- fused: edge pass 2 + layer-2 MLP + Q head + cleanup ------
__global__ void __launch_bounds__(512) k_final2(
        const void* __restrict__ ei, const float* __restrict__ ea,
        const void* __restrict__ curr, const void* __restrict__ dest,
        const void* __restrict__ nbr,
        const float* __restrict__ We2, const float* __restrict__ be2,
        const float* __restrict__ W2a, const float* __restrict__ b2a,
        const float* __restrict__ W2b, const float* __restrict__ b2b,
        const float* __restrict__ Wl1, const float* __restrict__ bl1,
        const float* __restrict__ Wl2, const float* __restrict__ bl2,
        float* __restrict__ out, int E, int K) {
    __shared__ __align__(16) float w[Hd];
    __shared__ __align__(16) float b[Hd];
    __shared__ __align__(16) float sA[NTGT * Hd];   // agg2, then sT = h1+agg2
    __shared__ __align__(16) float sU[NTGT * Hd];
    __shared__ __align__(16) float sH2[NTGT * Hd];
    __shared__ __align__(16) float sZ[MAXK * Hd];
    __shared__ __align__(16) float cd[Hd];
    __shared__ int tg[NTGT];

    int tid = threadIdx.x;
    int nt = 2 + K;
    int is64 = g_is64;

    if (tid < NTGT) {
        int v = -1;
        if (tid == 0)      v = load_idx(curr, 0, is64);
        else if (tid == 1) v = load_idx(dest, 0, is64);
        else if (tid < 2 + K) v = load_idx(nbr, tid - 2, is64);
        tg[tid] = v;
    }
    if (tid < Hd) { w[tid] = We2[tid]; b[tid] = be2[tid]; }
    for (int i = tid; i < NTGT * Hd; i += 512) sA[i] = 0.f;
    __syncthreads();

    // ---- edge pass 2 over pre-filtered list, accumulate into smem ----
    int count = g_ne2;
    for (int idx = tid; idx < count * 16; idx += 512) {
        int e = g_elist2[idx >> 4];
        int l = idx & 15;
        int d;
        long long s;
        if (is64) {
            s = ((const long long*)ei)[e];
            d = (int)((const long long*)ei)[E + e];
        } else {
            s = (long long)((const int*)ei)[e];
            d = ((const int*)ei)[E + e];
        }
        float a = __ldg(&ea[e]);
        float4 xv = *((const float4*)(g_h1 + s * Hd) + l);
        float4 wv = ((const float4*)w)[l];
        float4 bv = ((const float4*)b)[l];
        float4 m;
        m.x = fmaxf(xv.x + fmaf(a, wv.x, bv.x), 0.f);
        m.y = fmaxf(xv.y + fmaf(a, wv.y, bv.y), 0.f);
        m.z = fmaxf(xv.z + fmaf(a, wv.z, bv.z), 0.f);
        m.w = fmaxf(xv.w + fmaf(a, wv.w, bv.w), 0.f);
        #pragma unroll
        for (int t = 0; t < NTGT; t++) {
            if (d == tg[t]) {
                float* base2 = &sA[t * Hd + l * 4];
                atomicAdd(base2 + 0, m.x);
                atomicAdd(base2 + 1, m.y);
                atomicAdd(base2 + 2, m.z);
                atomicAdd(base2 + 3, m.w);
            }
        }
    }
    __syncthreads();

    // ---- sT = h1[target] + agg2 ----
    for (int i = tid; i < nt * Hd; i += 512) {
        int slot = i >> 6, j = i & 63;
        sA[i] += g_h1[(size_t)tg[slot] * Hd + j];
    }
    __syncthreads();

    // ---- mlp2 layer A ----
    for (int i = tid; i < nt * Hd; i += 512) {
        int slot = i >> 6, j = i & 63;
        float acc = b2a[j];
        const float* t = &sA[slot * Hd];
        #pragma unroll 16
        for (int k = 0; k < Hd; k++) acc = fmaf(t[k], __ldg(&W2a[k * Hd + j]), acc);
        sU[i] = fmaxf(acc, 0.f);
    }
    __syncthreads();

    // ---- mlp2 layer B (no relu) ----
    for (int i = tid; i < nt * Hd; i += 512) {
        int slot = i >> 6, j = i & 63;
        float acc = b2b[j];
        const float* u = &sU[slot * Hd];
        #pragma unroll 16
        for (int k = 0; k < Hd; k++) acc = fmaf(u[k], __ldg(&W2b[k * Hd + j]), acc);
        sH2[i] = acc;
    }
    __syncthreads();

    // ---- curr+dest part of lin1 ----
    if (tid < Hd) {
        float acc = bl1[tid];
        #pragma unroll 16
        for (int t = 0; t < Hd; t++)
            acc = fmaf(sH2[t], __ldg(&Wl1[t * Hd + tid]), acc);
        #pragma unroll 16
        for (int t = 0; t < Hd; t++)
            acc = fmaf(sH2[Hd + t], __ldg(&Wl1[(Hd + t) * Hd + tid]), acc);
        cd[tid] = acc;
    }
    __syncthreads();

    // ---- lin1 per neighbor + relu ----
    for (int i = tid; i < K * Hd; i += 512) {
        int k = i >> 6, j = i & 63;
        float acc = cd[j];
        const float* nb = &sH2[(2 + k) * Hd];
        #pragma unroll 16
        for (int t = 0; t < Hd; t++)
            acc = fmaf(nb[t], __ldg(&Wl1[(2 * Hd + t) * Hd + j]), acc);
        sZ[i] = fmaxf(acc, 0.f);
    }
    __syncthreads();

    // ---- lin2 ----
    if (tid < K) {
        float acc = bl2[0];
        #pragma unroll 16
        for (int j = 0; j < Hd; j++) acc = fmaf(sZ[tid * Hd + j], Wl2[j], acc);
        out[tid] = acc;
    }

    // ---- cleanup: restore the clean-state invariant for the next call ----
    int ns1 = g_ns1;
    for (int i = tid; i < ns1; i += 512) g_bitmap[g_s1[i] >> 5] = 0u;
    if (tid == 0) { g_ns1 = 0; g_ne2 = 0; }
}

// ---------------- launcher ----------------
extern "C" void kernel_launch(void* const* d_in, const int* in_sizes, int n_in,
                              void* d_out, int out_size) {
    const float* x    = (const float*)d_in[0];
    const void*  ei   = d_in[1];
    const void*  curr = d_in[2];
    const void*  dest = d_in[3];
    const void*  nbr  = d_in[4];
    const float* ea   = (const float*)d_in[5];
    const float* We1  = (const float*)d_in[6];
    const float* be1  = (const float*)d_in[7];
    const float* W1a  = (const float*)d_in[8];
    const float* b1a  = (const float*)d_in[9];
    const float* W1b  = (const float*)d_in[10];
    const float* b1b  = (const float*)d_in[11];
    const float* We2  = (const float*)d_in[12];
    const float* be2  = (const float*)d_in[13];
    const float* W2a  = (const float*)d_in[14];
    const float* b2a  = (const float*)d_in[15];
    const float* W2b  = (const float*)d_in[16];
    const float* b2b  = (const float*)d_in[17];
    const float* Wl1  = (const float*)d_in[18];
    const float* bl1  = (const float*)d_in[19];
    const float* Wl2  = (const float*)d_in[20];
    const float* bl2  = (const float*)d_in[21];

    int N = in_sizes[0] / Hd;
    int E = in_sizes[5];
    int K = in_sizes[4];
    if (K > MAXK) K = MAXK;

    int scan_blocks = (E + 1023) / 1024;   // one 16B chunk per thread

    k_scanA<<<scan_blocks, 256>>>(ei, curr, dest, nbr, E, (long long)N, K);
    k_scanB<<<scan_blocks, 256>>>(x, ei, ea, We1, be1, E);
    k_mlp1v2<<<160, 256>>>(x, W1a, b1a, W1b, b1b);
    k_final2<<<1, 512>>>(ei, ea, curr, dest, nbr, We2, be2,
                         W2a, b2a, W2b, b2b, Wl1, bl1, Wl2, bl2,
                         (float*)d_out, E, K);
}

// round 11
// speedup vs baseline: 1.7178x; 1.1452x over previous
#include <cuda_runtime.h>
#include <cuda_bf16.h>
#include <cstdint>

#define MAXN 50000
#define MAXE 800000
#define Hd   64
#define MAXK 16
#define NTGT (2 + MAXK)

// ---------------- device scratch (no allocs allowed) ----------------
// INVARIANT: g_bitmap is all-zero and g_ns1 == g_ne2 == 0 at every
// kernel_launch entry (zero-initialized at load; k_final2 restores it).
static __device__ float    g_agg1[(size_t)MAXN * Hd]; // layer-1 agg (S1 rows only)
static __device__ float    g_h1[(size_t)MAXN * Hd];   // relu(conv1 out) (S1 rows only)
static __device__ int      g_is64;
static __device__ unsigned g_bitmap[(MAXN + 31) / 32];// membership of S1
static __device__ int      g_s1[MAXN];                // S1 node list
static __device__ int      g_ns1;
static __device__ int      g_e2src[MAXE];             // per (edge,target) match: src node
static __device__ int      g_e2slot[MAXE];            //   target slot 0..17
static __device__ float    g_e2a[MAXE];               //   edge attr
static __device__ int      g_ne2;

__device__ __forceinline__ void zero_agg1_row(int node) {
    float4* p = (float4*)(g_agg1 + (size_t)node * Hd);
    #pragma unroll
    for (int i = 0; i < 16; i++) p[i] = make_float4(0.f, 0.f, 0.f, 0.f);
}

__device__ __forceinline__ int sniff_is64(const void* ei, int E, long long N) {
    const long long* p = (const long long*)ei;
    int n = E < 8 ? E : 8;
    int ok = 1;
    for (int q = 0; q < n; q++) {
        long long v = p[q];
        if (v < 0 || v >= N) { ok = 0; break; }
    }
    return ok;
}

__device__ __forceinline__ int load_idx(const void* p, int i, int is64) {
    return is64 ? (int)((const long long*)p)[i] : ((const int*)p)[i];
}

// ---------------- scan A: edges with dst in targets; build S1 + e2 payload --
__global__ void __launch_bounds__(256) k_scanA(
        const void* __restrict__ ei, const float* __restrict__ ea,
        const void* __restrict__ curr, const void* __restrict__ dest,
        const void* __restrict__ nbr, int E, long long N, int K) {
    __shared__ int tg[NTGT];
    __shared__ int s_is64;
    int tid = threadIdx.x;
    if (tid == 0) {
        int ok = sniff_is64(ei, E, N);
        s_is64 = ok;
        if (blockIdx.x == 0) g_is64 = ok;
    }
    __syncthreads();
    int is64 = s_is64;
    if (tid < NTGT) {
        int v = -1;
        if (tid == 0)      v = load_idx(curr, 0, is64);
        else if (tid == 1) v = load_idx(dest, 0, is64);
        else if (tid < 2 + K) v = load_idx(nbr, tid - 2, is64);
        tg[tid] = v;
    }
    __syncthreads();

    // block 0 seeds S1 with the targets
    if (blockIdx.x == 0 && tid < 2 + K) {
        int v = tg[tid];
        unsigned bit = 1u << (v & 31);
        unsigned old = atomicOr(&g_bitmap[v >> 5], bit);
        if (!(old & bit)) {
            int sl = atomicAdd(&g_ns1, 1);
            g_s1[sl] = v;
            zero_agg1_row(v);
        }
    }

    int base = (blockIdx.x * 256 + tid) * 4;
    if (base >= E) return;

    int dv[4];
    if (base + 4 <= E) {
        if (is64) {
            const long long* p = (const long long*)ei + E + base;
            longlong2 a = *(const longlong2*)p;
            longlong2 c = *(const longlong2*)(p + 2);
            dv[0] = (int)a.x; dv[1] = (int)a.y; dv[2] = (int)c.x; dv[3] = (int)c.y;
        } else {
            int4 a = *(const int4*)((const int*)ei + E + base);
            dv[0] = a.x; dv[1] = a.y; dv[2] = a.z; dv[3] = a.w;
        }
    } else {
        for (int j = 0; j < 4; j++)
            dv[j] = (base + j < E) ? load_idx(ei, E + base + j, is64) : -1;
    }

    #pragma unroll
    for (int j = 0; j < 4; j++) {
        int d = dv[j];
        bool match = false;
        #pragma unroll
        for (int t = 0; t < NTGT; t++) match |= (d == tg[t]);
        if (!match) continue;
        int e = base + j;
        int s = load_idx(ei, e, is64);
        float a = __ldg(&ea[e]);
        #pragma unroll
        for (int t = 0; t < NTGT; t++) {
            if (d == tg[t]) {
                int pos = atomicAdd(&g_ne2, 1);
                if (pos < MAXE) {
                    g_e2src[pos]  = s;
                    g_e2slot[pos] = t;
                    g_e2a[pos]    = a;
                }
            }
        }
        unsigned bit = 1u << (s & 31);
        unsigned old = atomicOr(&g_bitmap[s >> 5], bit);
        if (!(old & bit)) {
            int sl = atomicAdd(&g_ns1, 1);
            g_s1[sl] = s;
            zero_agg1_row(s);
        }
    }
}

// ---------------- scan B + edge pass 1, warp-cooperative -------------------
__global__ void __launch_bounds__(256) k_scanB(
        const float* __restrict__ x, const void* __restrict__ ei,
        const float* __restrict__ ea, const float* __restrict__ We1,
        const float* __restrict__ be1, int E) {
    int tid  = threadIdx.x;
    int lane = tid & 31;
    int is64 = g_is64;
    int base = (blockIdx.x * 256 + tid) * 4;

    float2 wv = *((const float2*)We1 + lane);
    float2 bv = *((const float2*)be1 + lane);

    int dv[4];
    if (base < E) {
        if (base + 4 <= E) {
            if (is64) {
                const long long* p = (const long long*)ei + E + base;
                longlong2 a = *(const longlong2*)p;
                longlong2 c = *(const longlong2*)(p + 2);
                dv[0] = (int)a.x; dv[1] = (int)a.y; dv[2] = (int)c.x; dv[3] = (int)c.y;
            } else {
                int4 a = *(const int4*)((const int*)ei + E + base);
                dv[0] = a.x; dv[1] = a.y; dv[2] = a.z; dv[3] = a.w;
            }
        } else {
            for (int j = 0; j < 4; j++)
                dv[j] = (base + j < E) ? load_idx(ei, E + base + j, is64) : -1;
        }
    } else {
        dv[0] = dv[1] = dv[2] = dv[3] = -1;
    }

    #pragma unroll
    for (int j = 0; j < 4; j++) {
        int d = dv[j];
        bool hit = (d >= 0) && ((g_bitmap[d >> 5] >> (d & 31)) & 1u);
        unsigned m = __ballot_sync(0xffffffffu, hit);
        while (m) {
            int src_lane = __ffs(m) - 1;
            m &= m - 1;
            int e  = __shfl_sync(0xffffffffu, base + j, src_lane);
            int dd = __shfl_sync(0xffffffffu, d, src_lane);
            long long s = is64 ? ((const long long*)ei)[e]
                               : (long long)((const int*)ei)[e];
            float a = __ldg(&ea[e]);
            float2 xv = *((const float2*)(x + s * Hd) + lane);
            float m0 = fmaxf(xv.x + fmaf(a, wv.x, bv.x), 0.f);
            float m1 = fmaxf(xv.y + fmaf(a, wv.y, bv.y), 0.f);
            float* dp = g_agg1 + (size_t)dd * Hd + 2 * lane;
            asm volatile("red.global.add.v2.f32 [%0], {%1,%2};"
                         :: "l"(dp), "f"(m0), "f"(m1) : "memory");
        }
    }
}

// ---------------- layer-1 MLP at S1 nodes ----------------------------------
__global__ void __launch_bounds__(256) k_mlp1v2(
        const float* __restrict__ x,
        const float* __restrict__ Wa, const float* __restrict__ ba,
        const float* __restrict__ Wb, const float* __restrict__ bb) {
    __shared__ __align__(16) float sIn[4 * Hd];
    __shared__ __align__(16) float sU[4 * Hd];

    int tid = threadIdx.x;
    int nl  = tid >> 6;
    int j   = tid & 63;
    int ns1 = g_ns1;

    for (int base = blockIdx.x * 4; base < ns1; base += gridDim.x * 4) {
        int idx = base + nl;
        bool valid = (idx < ns1);

        if (valid) {
            size_t node = (size_t)g_s1[idx];
            sIn[tid] = x[node * Hd + j] + g_agg1[node * Hd + j];
        } else {
            sIn[tid] = 0.f;
        }
        __syncthreads();

        {
            float acc = __ldg(&ba[j]);
            const float* in = &sIn[nl * Hd];
            #pragma unroll 16
            for (int k = 0; k < Hd; k++)
                acc = fmaf(in[k], __ldg(&Wa[k * Hd + j]), acc);
            sU[tid] = fmaxf(acc, 0.f);
        }
        __syncthreads();

        {
            float acc = __ldg(&bb[j]);
            const float* u = &sU[nl * Hd];
            #pragma unroll 16
            for (int k = 0; k < Hd; k++)
                acc = fmaf(u[k], __ldg(&Wb[k * Hd + j]), acc);
            if (valid) {
                size_t node = (size_t)g_s1[idx];
                g_h1[node * Hd + j] = fmaxf(acc, 0.f);
            }
        }
        __syncthreads();
    }
}

// ---------------- fused: edge pass 2 + layer-2 MLP + Q head + cleanup ------
__global__ void __launch_bounds__(512) k_final2(
        const float* __restrict__ We2, const float* __restrict__ be2,
        const void* __restrict__ curr, const void* __restrict__ dest,
        const void* __restrict__ nbr,
        const float* __restrict__ W2a, const float* __restrict__ b2a,
        const float* __restrict__ W2b, const float* __restrict__ b2b,
        const float* __restrict__ Wl1, const float* __restrict__ bl1,
        const float* __restrict__ Wl2, const float* __restrict__ bl2,
        float* __restrict__ out, int K) {
    __shared__ __align__(16) float w[Hd];
    __shared__ __align__(16) float b[Hd];
    __shared__ __align__(16) float sA[NTGT * Hd];   // agg2, then sT = h1+agg2
    __shared__ __align__(16) float sU[NTGT * Hd];
    __shared__ __align__(16) float sH2[NTGT * Hd];
    __shared__ __align__(16) float sZ[MAXK * Hd];
    __shared__ __align__(16) float cd[Hd];
    __shared__ int tg[NTGT];

    int tid = threadIdx.x;
    int nt = 2 + K;
    int is64 = g_is64;

    if (tid < NTGT) {
        int v = -1;
        if (tid == 0)      v = load_idx(curr, 0, is64);
        else if (tid == 1) v = load_idx(dest, 0, is64);
        else if (tid < 2 + K) v = load_idx(nbr, tid - 2, is64);
        tg[tid] = v;
    }
    if (tid < Hd) { w[tid] = We2[tid]; b[tid] = be2[tid]; }
    for (int i = tid; i < NTGT * Hd; i += 512) sA[i] = 0.f;
    __syncthreads();

    // ---- prefetch h1[target] rows into registers (overlaps edge pass) ----
    float h1t[3];
    {
        int c = 0;
        for (int i = tid; i < nt * Hd; i += 512, c++)
            h1t[c] = g_h1[(size_t)tg[i >> 6] * Hd + (i & 63)];
    }

    // ---- edge pass 2: precomputed (src, slot, a) payload; depth-2 chain ----
    int count = g_ne2;
    if (count > MAXE) count = MAXE;
    for (int idx = tid; idx < count * 16; idx += 512) {
        int ent = idx >> 4;
        int l = idx & 15;
        int s    = g_e2src[ent];
        int slot = g_e2slot[ent];
        float a  = g_e2a[ent];
        float4 xv = *((const float4*)(g_h1 + (size_t)s * Hd) + l);
        float4 wv = ((const float4*)w)[l];
        float4 bv = ((const float4*)b)[l];
        float* base2 = &sA[slot * Hd + l * 4];
        atomicAdd(base2 + 0, fmaxf(xv.x + fmaf(a, wv.x, bv.x), 0.f));
        atomicAdd(base2 + 1, fmaxf(xv.y + fmaf(a, wv.y, bv.y), 0.f));
        atomicAdd(base2 + 2, fmaxf(xv.z + fmaf(a, wv.z, bv.z), 0.f));
        atomicAdd(base2 + 3, fmaxf(xv.w + fmaf(a, wv.w, bv.w), 0.f));
    }
    __syncthreads();

    // ---- sT = h1[target] + agg2 (h1 already in registers) ----
    {
        int c = 0;
        for (int i = tid; i < nt * Hd; i += 512, c++)
            sA[i] += h1t[c];
    }
    __syncthreads();

    // ---- mlp2 layer A ----
    for (int i = tid; i < nt * Hd; i += 512) {
        int slot = i >> 6, j = i & 63;
        float acc = b2a[j];
        const float* t = &sA[slot * Hd];
        #pragma unroll 16
        for (int k = 0; k < Hd; k++) acc = fmaf(t[k], __ldg(&W2a[k * Hd + j]), acc);
        sU[i] = fmaxf(acc, 0.f);
    }
    __syncthreads();

    // ---- mlp2 layer B (no relu) ----
    for (int i = tid; i < nt * Hd; i += 512) {
        int slot = i >> 6, j = i & 63;
        float acc = b2b[j];
        const float* u = &sU[slot * Hd];
        #pragma unroll 16
        for (int k = 0; k < Hd; k++) acc = fmaf(u[k], __ldg(&W2b[k * Hd + j]), acc);
        sH2[i] = acc;
    }
    __syncthreads();

    // ---- curr+dest part of lin1 ----
    if (tid < Hd) {
        float acc = bl1[tid];
        #pragma unroll 16
        for (int t = 0; t < Hd; t++)
            acc = fmaf(sH2[t], __ldg(&Wl1[t * Hd + tid]), acc);
        #pragma unroll 16
        for (int t = 0; t < Hd; t++)
            acc = fmaf(sH2[Hd + t], __ldg(&Wl1[(Hd + t) * Hd + tid]), acc);
        cd[tid] = acc;
    }
    __syncthreads();

    // ---- lin1 per neighbor + relu ----
    for (int i = tid; i < K * Hd; i += 512) {
        int k = i >> 6, j = i & 63;
        float acc = cd[j];
        const float* nb = &sH2[(2 + k) * Hd];
        #pragma unroll 16
        for (int t = 0; t < Hd; t++)
            acc = fmaf(nb[t], __ldg(&Wl1[(2 * Hd + t) * Hd + j]), acc);
        sZ[i] = fmaxf(acc, 0.f);
    }
    __syncthreads();

    // ---- lin2 ----
    if (tid < K) {
        float acc = bl2[0];
        #pragma unroll 16
        for (int j = 0; j < Hd; j++) acc = fmaf(sZ[tid * Hd + j], Wl2[j], acc);
        out[tid] = acc;
    }

    // ---- cleanup: restore the clean-state invariant for the next call ----
    int ns1 = g_ns1;
    for (int i = tid; i < ns1; i += 512) g_bitmap[g_s1[i] >> 5] = 0u;
    if (tid == 0) { g_ns1 = 0; g_ne2 = 0; }
}

// ---------------- launcher ----------------
extern "C" void kernel_launch(void* const* d_in, const int* in_sizes, int n_in,
                              void* d_out, int out_size) {
    const float* x    = (const float*)d_in[0];
    const void*  ei   = d_in[1];
    const void*  curr = d_in[2];
    const void*  dest = d_in[3];
    const void*  nbr  = d_in[4];
    const float* ea   = (const float*)d_in[5];
    const float* We1  = (const float*)d_in[6];
    const float* be1  = (const float*)d_in[7];
    const float* W1a  = (const float*)d_in[8];
    const float* b1a  = (const float*)d_in[9];
    const float* W1b  = (const float*)d_in[10];
    const float* b1b  = (const float*)d_in[11];
    const float* We2  = (const float*)d_in[12];
    const float* be2  = (const float*)d_in[13];
    const float* W2a  = (const float*)d_in[14];
    const float* b2a  = (const float*)d_in[15];
    const float* W2b  = (const float*)d_in[16];
    const float* b2b  = (const float*)d_in[17];
    const float* Wl1  = (const float*)d_in[18];
    const float* bl1  = (const float*)d_in[19];
    const float* Wl2  = (const float*)d_in[20];
    const float* bl2  = (const float*)d_in[21];

    int N = in_sizes[0] / Hd;
    int E = in_sizes[5];
    int K = in_sizes[4];
    if (K > MAXK) K = MAXK;

    int scan_blocks = (E + 1023) / 1024;   // one 16B chunk per thread

    k_scanA<<<scan_blocks, 256>>>(ei, ea, curr, dest, nbr, E, (long long)N, K);
    k_scanB<<<scan_blocks, 256>>>(x, ei, ea, We1, be1, E);
    k_mlp1v2<<<160, 256>>>(x, W1a, b1a, W1b, b1b);
    k_final2<<<1, 512>>>(We2, be2, curr, dest, nbr,
                         W2a, b2a, W2b, b2b, Wl1, bl1, Wl2, bl2,
                         (float*)d_out, K);
}

// round 12
// speedup vs baseline: 1.7709x; 1.0309x over previous
#include <cuda_runtime.h>
#include <cuda_bf16.h>
#include <cstdint>

#define MAXN 50000
#define MAXE 800000
#define Hd   64
#define MAXK 16
#define NTGT (2 + MAXK)

// ---------------- device scratch (no allocs allowed) ----------------
// INVARIANT: g_bitmap all-zero and g_ns1 == g_ne2 == 0 at every
// kernel_launch entry (zero-init at load; k_mlpfinal restores it).
static __device__ float    g_agg1[(size_t)MAXN * Hd];
static __device__ float    g_h1[(size_t)MAXN * Hd];
static __device__ int      g_is64;
static __device__ unsigned g_bitmap[(MAXN + 31) / 32];
static __device__ int      g_s1[MAXN];
static __device__ int      g_ns1;
static __device__ int      g_e2src[MAXE];   // per (edge,target) match: src node
static __device__ int      g_e2slot[MAXE];  //   target slot 0..17
static __device__ float    g_e2a[MAXE];     //   edge attr
static __device__ int      g_ne2;

// grid barrier (sense-reversing; gen monotonic across calls, count self-resets)
static __device__ volatile unsigned g_gen;
static __device__ unsigned g_count;

__device__ __forceinline__ void grid_barrier() {
    __syncthreads();
    if (threadIdx.x == 0) {
        __threadfence();
        unsigned old = g_gen;
        if (atomicAdd(&g_count, 1) + 1 == gridDim.x) {
            g_count = 0;
            __threadfence();
            atomicExch((unsigned*)&g_gen, old + 1);
        } else {
            while (g_gen == old) __nanosleep(64);
        }
        __threadfence();
    }
    __syncthreads();
}

__device__ __forceinline__ void zero_agg1_row(int node) {
    float4* p = (float4*)(g_agg1 + (size_t)node * Hd);
    #pragma unroll
    for (int i = 0; i < 16; i++) p[i] = make_float4(0.f, 0.f, 0.f, 0.f);
}

__device__ __forceinline__ int sniff_is64(const void* ei, int E, long long N) {
    const long long* p = (const long long*)ei;
    int n = E < 8 ? E : 8;
    int ok = 1;
    for (int q = 0; q < n; q++) {
        long long v = p[q];
        if (v < 0 || v >= N) { ok = 0; break; }
    }
    return ok;
}

__device__ __forceinline__ int load_idx(const void* p, int i, int is64) {
    return is64 ? (int)((const long long*)p)[i] : ((const int*)p)[i];
}

// ============ kernel 1: scanA + grid barrier + scanB/edge1 ==================
__global__ void __launch_bounds__(256) k_scanAB(
        const float* __restrict__ x, const void* __restrict__ ei,
        const float* __restrict__ ea,
        const void* __restrict__ curr, const void* __restrict__ dest,
        const void* __restrict__ nbr,
        const float* __restrict__ We1, const float* __restrict__ be1,
        int E, long long N, int K) {
    __shared__ int tg[NTGT];
    __shared__ int s_is64;
    int tid  = threadIdx.x;
    int lane = tid & 31;
    int base = (blockIdx.x * 256 + tid) * 4;

    if (tid == 0) {
        int ok = sniff_is64(ei, E, N);
        s_is64 = ok;
        if (blockIdx.x == 0) g_is64 = ok;
    }
    __syncthreads();
    int is64 = s_is64;

    if (tid < NTGT) {
        int v = -1;
        if (tid == 0)      v = load_idx(curr, 0, is64);
        else if (tid == 1) v = load_idx(dest, 0, is64);
        else if (tid < 2 + K) v = load_idx(nbr, tid - 2, is64);
        tg[tid] = v;
    }
    __syncthreads();

    if (blockIdx.x == 0 && tid < 2 + K) {
        int v = tg[tid];
        unsigned bit = 1u << (v & 31);
        unsigned old = atomicOr(&g_bitmap[v >> 5], bit);
        if (!(old & bit)) {
            int sl = atomicAdd(&g_ns1, 1);
            g_s1[sl] = v;
            zero_agg1_row(v);
        }
    }

    // load this thread's 4 dst values once; reused by both phases
    int dv[4];
    if (base < E) {
        if (base + 4 <= E) {
            if (is64) {
                const long long* p = (const long long*)ei + E + base;
                longlong2 a = *(const longlong2*)p;
                longlong2 c = *(const longlong2*)(p + 2);
                dv[0] = (int)a.x; dv[1] = (int)a.y; dv[2] = (int)c.x; dv[3] = (int)c.y;
            } else {
                int4 a = *(const int4*)((const int*)ei + E + base);
                dv[0] = a.x; dv[1] = a.y; dv[2] = a.z; dv[3] = a.w;
            }
        } else {
            for (int j = 0; j < 4; j++)
                dv[j] = (base + j < E) ? load_idx(ei, E + base + j, is64) : -1;
        }
    } else {
        dv[0] = dv[1] = dv[2] = dv[3] = -1;
    }

    // ---- phase A: target hits -> e2 payload + S1 growth ----
    #pragma unroll
    for (int j = 0; j < 4; j++) {
        int d = dv[j];
        bool match = false;
        #pragma unroll
        for (int t = 0; t < NTGT; t++) match |= (d == tg[t]);
        if (!match) continue;
        int e = base + j;
        int s = load_idx(ei, e, is64);
        float a = __ldg(&ea[e]);
        #pragma unroll
        for (int t = 0; t < NTGT; t++) {
            if (d == tg[t]) {
                int pos = atomicAdd(&g_ne2, 1);
                if (pos < MAXE) {
                    g_e2src[pos]  = s;
                    g_e2slot[pos] = t;
                    g_e2a[pos]    = a;
                }
            }
        }
        unsigned bit = 1u << (s & 31);
        unsigned old = atomicOr(&g_bitmap[s >> 5], bit);
        if (!(old & bit)) {
            int sl = atomicAdd(&g_ns1, 1);
            g_s1[sl] = s;
            zero_agg1_row(s);
        }
    }

    grid_barrier();   // bitmap + agg1-row zeroing complete

    // ---- phase B: S1-bitmap hits -> edge pass 1, warp-cooperative ----
    float2 wv = *((const float2*)We1 + lane);
    float2 bv = *((const float2*)be1 + lane);

    #pragma unroll
    for (int j = 0; j < 4; j++) {
        int d = dv[j];
        bool hit = (d >= 0) && ((g_bitmap[d >> 5] >> (d & 31)) & 1u);
        unsigned m = __ballot_sync(0xffffffffu, hit);
        while (m) {
            int src_lane = __ffs(m) - 1;
            m &= m - 1;
            int e  = __shfl_sync(0xffffffffu, base + j, src_lane);
            int dd = __shfl_sync(0xffffffffu, d, src_lane);
            long long s = is64 ? ((const long long*)ei)[e]
                               : (long long)((const int*)ei)[e];
            float a = __ldg(&ea[e]);
            float2 xv = *((const float2*)(x + s * Hd) + lane);
            float m0 = fmaxf(xv.x + fmaf(a, wv.x, bv.x), 0.f);
            float m1 = fmaxf(xv.y + fmaf(a, wv.y, bv.y), 0.f);
            float* dp = g_agg1 + (size_t)dd * Hd + 2 * lane;
            asm volatile("red.global.add.v2.f32 [%0], {%1,%2};"
                         :: "l"(dp), "f"(m0), "f"(m1) : "memory");
        }
    }
}

// ============ kernel 2: layer-1 MLP + grid barrier + final (block 0) ========
__global__ void __launch_bounds__(512) k_mlpfinal(
        const float* __restrict__ x,
        const float* __restrict__ W1a, const float* __restrict__ b1a,
        const float* __restrict__ W1b, const float* __restrict__ b1b,
        const float* __restrict__ We2, const float* __restrict__ be2,
        const void* __restrict__ curr, const void* __restrict__ dest,
        const void* __restrict__ nbr,
        const float* __restrict__ W2a, const float* __restrict__ b2a,
        const float* __restrict__ W2b, const float* __restrict__ b2b,
        const float* __restrict__ Wl1, const float* __restrict__ bl1,
        const float* __restrict__ Wl2, const float* __restrict__ bl2,
        float* __restrict__ out, int K) {
    __shared__ __align__(16) float sIn[8 * Hd];
    __shared__ __align__(16) float sMu[8 * Hd];
    __shared__ __align__(16) float w[Hd];
    __shared__ __align__(16) float b[Hd];
    __shared__ __align__(16) float sA[NTGT * Hd];
    __shared__ __align__(16) float sU[NTGT * Hd];
    __shared__ __align__(16) float sH2[NTGT * Hd];
    __shared__ __align__(16) float sZ[MAXK * Hd];
    __shared__ __align__(16) float cd[Hd];
    __shared__ int tg[NTGT];

    int tid = threadIdx.x;
    int ns1 = g_ns1;

    // ---- phase 1: layer-1 MLP at S1 nodes (8 nodes/block, 512 threads) ----
    {
        int nl = tid >> 6;     // 0..7
        int j  = tid & 63;
        for (int base = blockIdx.x * 8; base < ns1; base += gridDim.x * 8) {
            int idx = base + nl;
            bool valid = (idx < ns1);
            if (valid) {
                size_t node = (size_t)g_s1[idx];
                sIn[tid] = x[node * Hd + j] + g_agg1[node * Hd + j];
            } else sIn[tid] = 0.f;
            __syncthreads();
            {
                float acc = __ldg(&b1a[j]);
                const float* in = &sIn[nl * Hd];
                #pragma unroll 16
                for (int k = 0; k < Hd; k++)
                    acc = fmaf(in[k], __ldg(&W1a[k * Hd + j]), acc);
                sMu[tid] = fmaxf(acc, 0.f);
            }
            __syncthreads();
            {
                float acc = __ldg(&b1b[j]);
                const float* u = &sMu[nl * Hd];
                #pragma unroll 16
                for (int k = 0; k < Hd; k++)
                    acc = fmaf(u[k], __ldg(&W1b[k * Hd + j]), acc);
                if (valid) {
                    size_t node = (size_t)g_s1[idx];
                    g_h1[node * Hd + j] = fmaxf(acc, 0.f);
                }
            }
            __syncthreads();
        }
    }

    grid_barrier();   // h1 complete everywhere

    if (blockIdx.x != 0) return;

    // ---- phase 2: edge pass 2 + layer-2 MLP + Q head + cleanup ----
    int nt = 2 + K;
    int is64 = g_is64;

    if (tid < NTGT) {
        int v = -1;
        if (tid == 0)      v = load_idx(curr, 0, is64);
        else if (tid == 1) v = load_idx(dest, 0, is64);
        else if (tid < 2 + K) v = load_idx(nbr, tid - 2, is64);
        tg[tid] = v;
    }
    if (tid < Hd) { w[tid] = We2[tid]; b[tid] = be2[tid]; }
    for (int i = tid; i < NTGT * Hd; i += 512) sA[i] = 0.f;
    __syncthreads();

    float h1t[3];
    {
        int c = 0;
        for (int i = tid; i < nt * Hd; i += 512, c++)
            h1t[c] = g_h1[(size_t)tg[i >> 6] * Hd + (i & 63)];
    }

    int count = g_ne2;
    if (count > MAXE) count = MAXE;
    for (int idx = tid; idx < count * 16; idx += 512) {
        int ent = idx >> 4;
        int l = idx & 15;
        int s    = g_e2src[ent];
        int slot = g_e2slot[ent];
        float a  = g_e2a[ent];
        float4 xv = *((const float4*)(g_h1 + (size_t)s * Hd) + l);
        float4 wv = ((const float4*)w)[l];
        float4 bv = ((const float4*)b)[l];
        float* base2 = &sA[slot * Hd + l * 4];
        atomicAdd(base2 + 0, fmaxf(xv.x + fmaf(a, wv.x, bv.x), 0.f));
        atomicAdd(base2 + 1, fmaxf(xv.y + fmaf(a, wv.y, bv.y), 0.f));
        atomicAdd(base2 + 2, fmaxf(xv.z + fmaf(a, wv.z, bv.z), 0.f));
        atomicAdd(base2 + 3, fmaxf(xv.w + fmaf(a, wv.w, bv.w), 0.f));
    }
    __syncthreads();

    {
        int c = 0;
        for (int i = tid; i < nt * Hd; i += 512, c++)
            sA[i] += h1t[c];
    }
    __syncthreads();

    for (int i = tid; i < nt * Hd; i += 512) {
        int slot = i >> 6, j = i & 63;
        float acc = b2a[j];
        const float* t = &sA[slot * Hd];
        #pragma unroll 16
        for (int k = 0; k < Hd; k++) acc = fmaf(t[k], __ldg(&W2a[k * Hd + j]), acc);
        sU[i] = fmaxf(acc, 0.f);
    }
    __syncthreads();

    for (int i = tid; i < nt * Hd; i += 512) {
        int slot = i >> 6, j = i & 63;
        float acc = b2b[j];
        const float* u = &sU[slot * Hd];
        #pragma unroll 16
        for (int k = 0; k < Hd; k++) acc = fmaf(u[k], __ldg(&W2b[k * Hd + j]), acc);
        sH2[i] = acc;
    }
    __syncthreads();

    if (tid < Hd) {
        float acc = bl1[tid];
        #pragma unroll 16
        for (int t = 0; t < Hd; t++)
            acc = fmaf(sH2[t], __ldg(&Wl1[t * Hd + tid]), acc);
        #pragma unroll 16
        for (int t = 0; t < Hd; t++)
            acc = fmaf(sH2[Hd + t], __ldg(&Wl1[(Hd + t) * Hd + tid]), acc);
        cd[tid] = acc;
    }
    __syncthreads();

    for (int i = tid; i < K * Hd; i += 512) {
        int k = i >> 6, j = i & 63;
        float acc = cd[j];
        const float* nb = &sH2[(2 + k) * Hd];
        #pragma unroll 16
        for (int t = 0; t < Hd; t++)
            acc = fmaf(nb[t], __ldg(&Wl1[(2 * Hd + t) * Hd + j]), acc);
        sZ[i] = fmaxf(acc, 0.f);
    }
    __syncthreads();

    if (tid < K) {
        float acc = bl2[0];
        #pragma unroll 16
        for (int j = 0; j < Hd; j++) acc = fmaf(sZ[tid * Hd + j], Wl2[j], acc);
        out[tid] = acc;
    }

    // ---- cleanup: restore the clean-state invariant for the next call ----
    for (int i = tid; i < ns1; i += 512) g_bitmap[g_s1[i] >> 5] = 0u;
    if (tid == 0) { g_ns1 = 0; g_ne2 = 0; }
}

// ---------------- launcher ----------------
extern "C" void kernel_launch(void* const* d_in, const int* in_sizes, int n_in,
                              void* d_out, int out_size) {
    const float* x    = (const float*)d_in[0];
    const void*  ei   = d_in[1];
    const void*  curr = d_in[2];
    const void*  dest = d_in[3];
    const void*  nbr  = d_in[4];
    const float* ea   = (const float*)d_in[5];
    const float* We1  = (const float*)d_in[6];
    const float* be1  = (const float*)d_in[7];
    const float* W1a  = (const float*)d_in[8];
    const float* b1a  = (const float*)d_in[9];
    const float* W1b  = (const float*)d_in[10];
    const float* b1b  = (const float*)d_in[11];
    const float* We2  = (const float*)d_in[12];
    const float* be2  = (const float*)d_in[13];
    const float* W2a  = (const float*)d_in[14];
    const float* b2a  = (const float*)d_in[15];
    const float* W2b  = (const float*)d_in[16];
    const float* b2b  = (const float*)d_in[17];
    const float* Wl1  = (const float*)d_in[18];
    const float* bl1  = (const float*)d_in[19];
    const float* Wl2  = (const float*)d_in[20];
    const float* bl2  = (const float*)d_in[21];

    int N = in_sizes[0] / Hd;
    int E = in_sizes[5];
    int K = in_sizes[4];
    if (K > MAXK) K = MAXK;

    int scan_blocks = (E + 1023) / 1024;   // 782 for E=800k; co-resident (<=1184)

    k_scanAB<<<scan_blocks, 256>>>(x, ei, ea, curr, dest, nbr, We1, be1,
                                   E, (long long)N, K);
    k_mlpfinal<<<160, 512>>>(x, W1a, b1a, W1b, b1b, We2, be2,
                             curr, dest, nbr, W2a, b2a, W2b, b2b,
                             Wl1, bl1, Wl2, bl2, (float*)d_out, K);
}

// round 13
// speedup vs baseline: 2.1429x; 1.2100x over previous
#include <cuda_runtime.h>
#include <cuda_bf16.h>
#include <cstdint>

#define MAXN 50000
#define MAXE 800000
#define Hd   64
#define MAXK 16
#define NTGT (2 + MAXK)

// ---------------- device scratch (no allocs allowed) ----------------
// INVARIANT: g_bitmap all-zero and g_ns1 == g_ne2 == 0 at every
// kernel_launch entry (zero-init at load; k_mlpfinal restores it).
static __device__ float    g_agg1[(size_t)MAXN * Hd];
static __device__ float    g_h1[(size_t)MAXN * Hd];
static __device__ float    g_h2[NTGT * Hd];          // conv2 output rows
static __device__ int      g_is64;
static __device__ unsigned g_bitmap[(MAXN + 31) / 32];
static __device__ int      g_s1[MAXN];
static __device__ int      g_ns1;
static __device__ int      g_e2src[MAXE];   // per (edge,target) match: src node
static __device__ int      g_e2slot[MAXE];  //   target slot 0..17
static __device__ float    g_e2a[MAXE];     //   edge attr
static __device__ int      g_ne2;

// grid barrier (sense-reversing; gen monotonic across calls, count self-resets)
static __device__ volatile unsigned g_gen;
static __device__ unsigned g_count;

__device__ __forceinline__ void grid_barrier() {
    __syncthreads();
    if (threadIdx.x == 0) {
        __threadfence();
        unsigned old = g_gen;
        if (atomicAdd(&g_count, 1) + 1 == gridDim.x) {
            g_count = 0;
            __threadfence();
            atomicExch((unsigned*)&g_gen, old + 1);
        } else {
            while (g_gen == old) __nanosleep(64);
        }
        __threadfence();
    }
    __syncthreads();
}

__device__ __forceinline__ void zero_agg1_row(int node) {
    float4* p = (float4*)(g_agg1 + (size_t)node * Hd);
    #pragma unroll
    for (int i = 0; i < 16; i++) p[i] = make_float4(0.f, 0.f, 0.f, 0.f);
}

__device__ __forceinline__ int sniff_is64(const void* ei, int E, long long N) {
    const long long* p = (const long long*)ei;
    int n = E < 8 ? E : 8;
    int ok = 1;
    for (int q = 0; q < n; q++) {
        long long v = p[q];
        if (v < 0 || v >= N) { ok = 0; break; }
    }
    return ok;
}

__device__ __forceinline__ int load_idx(const void* p, int i, int is64) {
    return is64 ? (int)((const long long*)p)[i] : ((const int*)p)[i];
}

// ============ kernel 1: scanA + grid barrier + scanB/edge1 ==================
__global__ void __launch_bounds__(256) k_scanAB(
        const float* __restrict__ x, const void* __restrict__ ei,
        const float* __restrict__ ea,
        const void* __restrict__ curr, const void* __restrict__ dest,
        const void* __restrict__ nbr,
        const float* __restrict__ We1, const float* __restrict__ be1,
        int E, long long N, int K) {
    __shared__ int tg[NTGT];
    __shared__ int s_is64;
    int tid  = threadIdx.x;
    int lane = tid & 31;
    int base = (blockIdx.x * 256 + tid) * 4;

    if (tid == 0) {
        int ok = sniff_is64(ei, E, N);
        s_is64 = ok;
        if (blockIdx.x == 0) g_is64 = ok;
    }
    __syncthreads();
    int is64 = s_is64;

    if (tid < NTGT) {
        int v = -1;
        if (tid == 0)      v = load_idx(curr, 0, is64);
        else if (tid == 1) v = load_idx(dest, 0, is64);
        else if (tid < 2 + K) v = load_idx(nbr, tid - 2, is64);
        tg[tid] = v;
    }
    __syncthreads();

    if (blockIdx.x == 0 && tid < 2 + K) {
        int v = tg[tid];
        unsigned bit = 1u << (v & 31);
        unsigned old = atomicOr(&g_bitmap[v >> 5], bit);
        if (!(old & bit)) {
            int sl = atomicAdd(&g_ns1, 1);
            g_s1[sl] = v;
            zero_agg1_row(v);
        }
    }

    // load this thread's 4 dst values once; reused by both phases
    int dv[4];
    if (base < E) {
        if (base + 4 <= E) {
            if (is64) {
                const long long* p = (const long long*)ei + E + base;
                longlong2 a = *(const longlong2*)p;
                longlong2 c = *(const longlong2*)(p + 2);
                dv[0] = (int)a.x; dv[1] = (int)a.y; dv[2] = (int)c.x; dv[3] = (int)c.y;
            } else {
                int4 a = *(const int4*)((const int*)ei + E + base);
                dv[0] = a.x; dv[1] = a.y; dv[2] = a.z; dv[3] = a.w;
            }
        } else {
            for (int j = 0; j < 4; j++)
                dv[j] = (base + j < E) ? load_idx(ei, E + base + j, is64) : -1;
        }
    } else {
        dv[0] = dv[1] = dv[2] = dv[3] = -1;
    }

    // ---- phase A: target hits -> e2 payload + S1 growth ----
    #pragma unroll
    for (int j = 0; j < 4; j++) {
        int d = dv[j];
        bool match = false;
        #pragma unroll
        for (int t = 0; t < NTGT; t++) match |= (d == tg[t]);
        if (!match) continue;
        int e = base + j;
        int s = load_idx(ei, e, is64);
        float a = __ldg(&ea[e]);
        #pragma unroll
        for (int t = 0; t < NTGT; t++) {
            if (d == tg[t]) {
                int pos = atomicAdd(&g_ne2, 1);
                if (pos < MAXE) {
                    g_e2src[pos]  = s;
                    g_e2slot[pos] = t;
                    g_e2a[pos]    = a;
                }
            }
        }
        unsigned bit = 1u << (s & 31);
        unsigned old = atomicOr(&g_bitmap[s >> 5], bit);
        if (!(old & bit)) {
            int sl = atomicAdd(&g_ns1, 1);
            g_s1[sl] = s;
            zero_agg1_row(s);
        }
    }

    grid_barrier();   // bitmap + agg1-row zeroing complete

    // ---- phase B: S1-bitmap hits -> edge pass 1, warp-cooperative ----
    float2 wv = *((const float2*)We1 + lane);
    float2 bv = *((const float2*)be1 + lane);

    #pragma unroll
    for (int j = 0; j < 4; j++) {
        int d = dv[j];
        bool hit = (d >= 0) && ((g_bitmap[d >> 5] >> (d & 31)) & 1u);
        unsigned m = __ballot_sync(0xffffffffu, hit);
        while (m) {
            int src_lane = __ffs(m) - 1;
            m &= m - 1;
            int e  = __shfl_sync(0xffffffffu, base + j, src_lane);
            int dd = __shfl_sync(0xffffffffu, d, src_lane);
            long long s = is64 ? ((const long long*)ei)[e]
                               : (long long)((const int*)ei)[e];
            float a = __ldg(&ea[e]);
            float2 xv = *((const float2*)(x + s * Hd) + lane);
            float m0 = fmaxf(xv.x + fmaf(a, wv.x, bv.x), 0.f);
            float m1 = fmaxf(xv.y + fmaf(a, wv.y, bv.y), 0.f);
            float* dp = g_agg1 + (size_t)dd * Hd + 2 * lane;
            asm volatile("red.global.add.v2.f32 [%0], {%1,%2};"
                         :: "l"(dp), "f"(m0), "f"(m1) : "memory");
        }
    }
}

// ============ kernel 2: mlp1 | barrier | conv2 x18 blocks | barrier | head ==
__global__ void __launch_bounds__(512) k_mlpfinal(
        const float* __restrict__ x,
        const float* __restrict__ W1a, const float* __restrict__ b1a,
        const float* __restrict__ W1b, const float* __restrict__ b1b,
        const float* __restrict__ We2, const float* __restrict__ be2,
        const void* __restrict__ curr, const void* __restrict__ dest,
        const void* __restrict__ nbr,
        const float* __restrict__ W2a, const float* __restrict__ b2a,
        const float* __restrict__ W2b, const float* __restrict__ b2b,
        const float* __restrict__ Wl1, const float* __restrict__ bl1,
        const float* __restrict__ Wl2, const float* __restrict__ bl2,
        float* __restrict__ out, int K) {
    __shared__ __align__(16) float sIn[8 * Hd];
    __shared__ __align__(16) float sMu[8 * Hd];
    __shared__ __align__(16) float sA[Hd];         // one target row
    __shared__ __align__(16) float sU[Hd];
    __shared__ __align__(16) float sH2[NTGT * Hd]; // phase-3 gather
    __shared__ __align__(16) float sZ[MAXK * Hd];
    __shared__ __align__(16) float cd[Hd];

    int tid = threadIdx.x;
    int bid = blockIdx.x;
    int ns1 = g_ns1;
    int nt  = 2 + K;
    int is64 = g_is64;

    // ---- phase 1: layer-1 MLP at S1 nodes (8 nodes/block) ----
    {
        int nl = tid >> 6;     // 0..7
        int j  = tid & 63;
        for (int base = bid * 8; base < ns1; base += gridDim.x * 8) {
            int idx = base + nl;
            bool valid = (idx < ns1);
            if (valid) {
                size_t node = (size_t)g_s1[idx];
                sIn[tid] = x[node * Hd + j] + g_agg1[node * Hd + j];
            } else sIn[tid] = 0.f;
            __syncthreads();
            {
                float acc = __ldg(&b1a[j]);
                const float* in = &sIn[nl * Hd];
                #pragma unroll 16
                for (int k = 0; k < Hd; k++)
                    acc = fmaf(in[k], __ldg(&W1a[k * Hd + j]), acc);
                sMu[tid] = fmaxf(acc, 0.f);
            }
            __syncthreads();
            {
                float acc = __ldg(&b1b[j]);
                const float* u = &sMu[nl * Hd];
                #pragma unroll 16
                for (int k = 0; k < Hd; k++)
                    acc = fmaf(u[k], __ldg(&W1b[k * Hd + j]), acc);
                if (valid) {
                    size_t node = (size_t)g_s1[idx];
                    g_h1[node * Hd + j] = fmaxf(acc, 0.f);
                }
            }
            __syncthreads();
        }
    }

    grid_barrier();   // h1 complete everywhere

    // ---- phase 2: conv2 for one target slot per block (blocks 0..nt-1) ----
    if (bid < nt) {
        int slot = bid;
        int tgv;
        if (slot == 0)      tgv = load_idx(curr, 0, is64);
        else if (slot == 1) tgv = load_idx(dest, 0, is64);
        else                tgv = load_idx(nbr, slot - 2, is64);

        if (tid < Hd) sA[tid] = 0.f;
        __syncthreads();

        // agg2 for this slot from the e2 payload (filter by slot)
        int count = g_ne2;
        if (count > MAXE) count = MAXE;
        for (int idx = tid; idx < count * 16; idx += 512) {
            int ent = idx >> 4;
            if (g_e2slot[ent] != slot) continue;
            int l = idx & 15;
            int s   = g_e2src[ent];
            float a = g_e2a[ent];
            float4 xv = *((const float4*)(g_h1 + (size_t)s * Hd) + l);
            float4 wv = __ldg((const float4*)We2 + l);
            float4 bv = __ldg((const float4*)be2 + l);
            float* base2 = &sA[l * 4];
            atomicAdd(base2 + 0, fmaxf(xv.x + fmaf(a, wv.x, bv.x), 0.f));
            atomicAdd(base2 + 1, fmaxf(xv.y + fmaf(a, wv.y, bv.y), 0.f));
            atomicAdd(base2 + 2, fmaxf(xv.z + fmaf(a, wv.z, bv.z), 0.f));
            atomicAdd(base2 + 3, fmaxf(xv.w + fmaf(a, wv.w, bv.w), 0.f));
        }
        __syncthreads();

        if (tid < Hd) sA[tid] += g_h1[(size_t)tgv * Hd + tid];
        __syncthreads();

        // mlp2A: 8 threads per output, split-K shfl reduce (depth 8)
        {
            int j   = tid >> 3;       // output 0..63
            int sub = tid & 7;        // k-slice
            float acc = 0.f;
            #pragma unroll
            for (int q = 0; q < 8; q++) {
                int k = sub * 8 + q;
                acc = fmaf(sA[k], __ldg(&W2a[k * Hd + j]), acc);
            }
            acc += __shfl_down_sync(0xffffffffu, acc, 4, 8);
            acc += __shfl_down_sync(0xffffffffu, acc, 2, 8);
            acc += __shfl_down_sync(0xffffffffu, acc, 1, 8);
            if (sub == 0) sU[j] = fmaxf(acc + __ldg(&b2a[j]), 0.f);
        }
        __syncthreads();

        // mlp2B (no relu), write h2 row to global
        {
            int j   = tid >> 3;
            int sub = tid & 7;
            float acc = 0.f;
            #pragma unroll
            for (int q = 0; q < 8; q++) {
                int k = sub * 8 + q;
                acc = fmaf(sU[k], __ldg(&W2b[k * Hd + j]), acc);
            }
            acc += __shfl_down_sync(0xffffffffu, acc, 4, 8);
            acc += __shfl_down_sync(0xffffffffu, acc, 2, 8);
            acc += __shfl_down_sync(0xffffffffu, acc, 1, 8);
            if (sub == 0) g_h2[slot * Hd + j] = acc + __ldg(&b2b[j]);
        }
    }

    grid_barrier();   // all h2 rows written

    if (bid != 0) return;

    // ---- phase 3: Q head (block 0) + cleanup ----
    for (int i = tid; i < nt * Hd; i += 512) sH2[i] = g_h2[i];
    __syncthreads();

    if (tid < Hd) {
        float acc = bl1[tid];
        #pragma unroll 16
        for (int t = 0; t < Hd; t++)
            acc = fmaf(sH2[t], __ldg(&Wl1[t * Hd + tid]), acc);
        #pragma unroll 16
        for (int t = 0; t < Hd; t++)
            acc = fmaf(sH2[Hd + t], __ldg(&Wl1[(Hd + t) * Hd + tid]), acc);
        cd[tid] = acc;
    }
    __syncthreads();

    for (int i = tid; i < K * Hd; i += 512) {
        int k = i >> 6, j = i & 63;
        float acc = cd[j];
        const float* nb = &sH2[(2 + k) * Hd];
        #pragma unroll 16
        for (int t = 0; t < Hd; t++)
            acc = fmaf(nb[t], __ldg(&Wl1[(2 * Hd + t) * Hd + j]), acc);
        sZ[i] = fmaxf(acc, 0.f);
    }
    __syncthreads();

    if (tid < K) {
        float acc = bl2[0];
        #pragma unroll 16
        for (int j = 0; j < Hd; j++) acc = fmaf(sZ[tid * Hd + j], Wl2[j], acc);
        out[tid] = acc;
    }

    // ---- cleanup: restore the clean-state invariant for the next call ----
    for (int i = tid; i < ns1; i += 512) g_bitmap[g_s1[i] >> 5] = 0u;
    if (tid == 0) { g_ns1 = 0; g_ne2 = 0; }
}

// ---------------- launcher ----------------
extern "C" void kernel_launch(void* const* d_in, const int* in_sizes, int n_in,
                              void* d_out, int out_size) {
    const float* x    = (const float*)d_in[0];
    const void*  ei   = d_in[1];
    const void*  curr = d_in[2];
    const void*  dest = d_in[3];
    const void*  nbr  = d_in[4];
    const float* ea   = (const float*)d_in[5];
    const float* We1  = (const float*)d_in[6];
    const float* be1  = (const float*)d_in[7];
    const float* W1a  = (const float*)d_in[8];
    const float* b1a  = (const float*)d_in[9];
    const float* W1b  = (const float*)d_in[10];
    const float* b1b  = (const float*)d_in[11];
    const float* We2  = (const float*)d_in[12];
    const float* be2  = (const float*)d_in[13];
    const float* W2a  = (const float*)d_in[14];
    const float* b2a  = (const float*)d_in[15];
    const float* W2b  = (const float*)d_in[16];
    const float* b2b  = (const float*)d_in[17];
    const float* Wl1  = (const float*)d_in[18];
    const float* bl1  = (const float*)d_in[19];
    const float* Wl2  = (const float*)d_in[20];
    const float* bl2  = (const float*)d_in[21];

    int N = in_sizes[0] / Hd;
    int E = in_sizes[5];
    int K = in_sizes[4];
    if (K > MAXK) K = MAXK;

    int scan_blocks = (E + 1023) / 1024;   // 782 for E=800k; co-resident (<=1184)

    k_scanAB<<<scan_blocks, 256>>>(x, ei, ea, curr, dest, nbr, We1, be1,
                                   E, (long long)N, K);
    k_mlpfinal<<<160, 512>>>(x, W1a, b1a, W1b, b1b, We2, be2,
                             curr, dest, nbr, W2a, b2a, W2b, b2b,
                             Wl1, bl1, Wl2, bl2, (float*)d_out, K);
}

// round 14
// speedup vs baseline: 2.4046x; 1.1221x over previous
#include <cuda_runtime.h>
#include <cuda_bf16.h>
#include <cstdint>

#define MAXN 50000
#define MAXE 800000
#define Hd   64
#define MAXK 16
#define NTGT (2 + MAXK)

// ---------------- device scratch (no allocs allowed) ----------------
// INVARIANT: g_bitmap all-zero and g_ns1 == g_ne2 == 0 at every
// kernel_launch entry (zero-init at load; k_mlpfinal restores it).
static __device__ float    g_agg1[(size_t)MAXN * Hd];
static __device__ float    g_h1[(size_t)MAXN * Hd];
static __device__ float    g_h2[NTGT * Hd];          // conv2 output rows
static __device__ int      g_is64;
static __device__ unsigned g_bitmap[(MAXN + 31) / 32];
static __device__ int      g_s1[MAXN];
static __device__ int      g_ns1;
static __device__ int      g_e2src[MAXE];   // per (edge,target) match: src node
static __device__ int      g_e2slot[MAXE];  //   target slot 0..17
static __device__ float    g_e2a[MAXE];     //   edge attr
static __device__ int      g_ne2;

// grid barrier (sense-reversing; gen monotonic across calls, count self-resets)
static __device__ volatile unsigned g_gen;
static __device__ unsigned g_count;

__device__ __forceinline__ void grid_barrier() {
    __syncthreads();
    if (threadIdx.x == 0) {
        __threadfence();
        unsigned old = g_gen;
        if (atomicAdd(&g_count, 1) + 1 == gridDim.x) {
            g_count = 0;
            __threadfence();
            atomicExch((unsigned*)&g_gen, old + 1);
        } else {
            while (g_gen == old) __nanosleep(64);
        }
        __threadfence();
    }
    __syncthreads();
}

__device__ __forceinline__ void zero_agg1_row(int node) {
    float4* p = (float4*)(g_agg1 + (size_t)node * Hd);
    #pragma unroll
    for (int i = 0; i < 16; i++) p[i] = make_float4(0.f, 0.f, 0.f, 0.f);
}

__device__ __forceinline__ int sniff_is64(const void* ei, int E, long long N) {
    const long long* p = (const long long*)ei;
    int n = E < 8 ? E : 8;
    int ok = 1;
    for (int q = 0; q < n; q++) {
        long long v = p[q];
        if (v < 0 || v >= N) { ok = 0; break; }
    }
    return ok;
}

__device__ __forceinline__ int load_idx(const void* p, int i, int is64) {
    return is64 ? (int)((const long long*)p)[i] : ((const int*)p)[i];
}

// ============ kernel 1: scanA + grid barrier + scanB/edge1 ==================
__global__ void __launch_bounds__(256) k_scanAB(
        const float* __restrict__ x, const void* __restrict__ ei,
        const float* __restrict__ ea,
        const void* __restrict__ curr, const void* __restrict__ dest,
        const void* __restrict__ nbr,
        const float* __restrict__ We1, const float* __restrict__ be1,
        int E, long long N, int K) {
    __shared__ int tg[NTGT];
    __shared__ int s_is64;
    int tid  = threadIdx.x;
    int lane = tid & 31;
    int base = (blockIdx.x * 256 + tid) * 4;

    if (tid == 0) {
        int ok = sniff_is64(ei, E, N);
        s_is64 = ok;
        if (blockIdx.x == 0) g_is64 = ok;
    }
    __syncthreads();
    int is64 = s_is64;

    if (tid < NTGT) {
        int v = -1;
        if (tid == 0)      v = load_idx(curr, 0, is64);
        else if (tid == 1) v = load_idx(dest, 0, is64);
        else if (tid < 2 + K) v = load_idx(nbr, tid - 2, is64);
        tg[tid] = v;
    }
    __syncthreads();

    if (blockIdx.x == 0 && tid < 2 + K) {
        int v = tg[tid];
        unsigned bit = 1u << (v & 31);
        unsigned old = atomicOr(&g_bitmap[v >> 5], bit);
        if (!(old & bit)) {
            int sl = atomicAdd(&g_ns1, 1);
            g_s1[sl] = v;
            zero_agg1_row(v);
        }
    }

    // load this thread's 4 dst values once; reused by both phases
    int dv[4];
    if (base < E) {
        if (base + 4 <= E) {
            if (is64) {
                const long long* p = (const long long*)ei + E + base;
                longlong2 a = *(const longlong2*)p;
                longlong2 c = *(const longlong2*)(p + 2);
                dv[0] = (int)a.x; dv[1] = (int)a.y; dv[2] = (int)c.x; dv[3] = (int)c.y;
            } else {
                int4 a = *(const int4*)((const int*)ei + E + base);
                dv[0] = a.x; dv[1] = a.y; dv[2] = a.z; dv[3] = a.w;
            }
        } else {
            for (int j = 0; j < 4; j++)
                dv[j] = (base + j < E) ? load_idx(ei, E + base + j, is64) : -1;
        }
    } else {
        dv[0] = dv[1] = dv[2] = dv[3] = -1;
    }

    // ---- phase A: target hits -> e2 payload + S1 growth ----
    #pragma unroll
    for (int j = 0; j < 4; j++) {
        int d = dv[j];
        bool match = false;
        #pragma unroll
        for (int t = 0; t < NTGT; t++) match |= (d == tg[t]);
        if (!match) continue;
        int e = base + j;
        int s = load_idx(ei, e, is64);
        float a = __ldg(&ea[e]);
        #pragma unroll
        for (int t = 0; t < NTGT; t++) {
            if (d == tg[t]) {
                int pos = atomicAdd(&g_ne2, 1);
                if (pos < MAXE) {
                    g_e2src[pos]  = s;
                    g_e2slot[pos] = t;
                    g_e2a[pos]    = a;
                }
            }
        }
        unsigned bit = 1u << (s & 31);
        unsigned old = atomicOr(&g_bitmap[s >> 5], bit);
        if (!(old & bit)) {
            int sl = atomicAdd(&g_ns1, 1);
            g_s1[sl] = s;
            zero_agg1_row(s);
        }
    }

    grid_barrier();   // bitmap + agg1-row zeroing complete

    // ---- phase B: S1-bitmap hits -> edge pass 1, warp-cooperative ----
    float2 wv = *((const float2*)We1 + lane);
    float2 bv = *((const float2*)be1 + lane);

    #pragma unroll
    for (int j = 0; j < 4; j++) {
        int d = dv[j];
        bool hit = (d >= 0) && ((g_bitmap[d >> 5] >> (d & 31)) & 1u);
        unsigned m = __ballot_sync(0xffffffffu, hit);
        while (m) {
            int src_lane = __ffs(m) - 1;
            m &= m - 1;
            int e  = __shfl_sync(0xffffffffu, base + j, src_lane);
            int dd = __shfl_sync(0xffffffffu, d, src_lane);
            long long s = is64 ? ((const long long*)ei)[e]
                               : (long long)((const int*)ei)[e];
            float a = __ldg(&ea[e]);
            float2 xv = *((const float2*)(x + s * Hd) + lane);
            float m0 = fmaxf(xv.x + fmaf(a, wv.x, bv.x), 0.f);
            float m1 = fmaxf(xv.y + fmaf(a, wv.y, bv.y), 0.f);
            float* dp = g_agg1 + (size_t)dd * Hd + 2 * lane;
            asm volatile("red.global.add.v2.f32 [%0], {%1,%2};"
                         :: "l"(dp), "f"(m0), "f"(m1) : "memory");
        }
    }
}

// ============ kernel 2: mlp1 | barrier | conv2 x18 | barrier | head x16 =====
__global__ void __launch_bounds__(512) k_mlpfinal(
        const float* __restrict__ x,
        const float* __restrict__ W1a, const float* __restrict__ b1a,
        const float* __restrict__ W1b, const float* __restrict__ b1b,
        const float* __restrict__ We2, const float* __restrict__ be2,
        const void* __restrict__ curr, const void* __restrict__ dest,
        const void* __restrict__ nbr,
        const float* __restrict__ W2a, const float* __restrict__ b2a,
        const float* __restrict__ W2b, const float* __restrict__ b2b,
        const float* __restrict__ Wl1, const float* __restrict__ bl1,
        const float* __restrict__ Wl2, const float* __restrict__ bl2,
        float* __restrict__ out, int K) {
    __shared__ __align__(16) float sIn[8 * Hd];
    __shared__ __align__(16) float sMu[8 * Hd];
    __shared__ __align__(16) float sA[Hd];       // one conv2 target row
    __shared__ __align__(16) float sU[Hd];
    __shared__ __align__(16) float sC[3 * Hd];   // head: [h2_curr, h2_dest, h2_nbr]
    __shared__ __align__(16) float sZ[Hd];       // head: relu(lin1) row

    int tid = threadIdx.x;
    int bid = blockIdx.x;
    int ns1 = g_ns1;
    int nt  = 2 + K;
    int is64 = g_is64;

    // ---- phase 1: layer-1 MLP at S1 nodes (8 nodes/block) ----
    {
        int nl = tid >> 6;     // 0..7
        int j  = tid & 63;
        for (int base = bid * 8; base < ns1; base += gridDim.x * 8) {
            int idx = base + nl;
            bool valid = (idx < ns1);
            if (valid) {
                size_t node = (size_t)g_s1[idx];
                sIn[tid] = x[node * Hd + j] + g_agg1[node * Hd + j];
            } else sIn[tid] = 0.f;
            __syncthreads();
            {
                float acc = __ldg(&b1a[j]);
                const float* in = &sIn[nl * Hd];
                #pragma unroll 16
                for (int k = 0; k < Hd; k++)
                    acc = fmaf(in[k], __ldg(&W1a[k * Hd + j]), acc);
                sMu[tid] = fmaxf(acc, 0.f);
            }
            __syncthreads();
            {
                float acc = __ldg(&b1b[j]);
                const float* u = &sMu[nl * Hd];
                #pragma unroll 16
                for (int k = 0; k < Hd; k++)
                    acc = fmaf(u[k], __ldg(&W1b[k * Hd + j]), acc);
                if (valid) {
                    size_t node = (size_t)g_s1[idx];
                    g_h1[node * Hd + j] = fmaxf(acc, 0.f);
                }
            }
            __syncthreads();
        }
    }

    grid_barrier();   // h1 complete everywhere

    // ---- phase 2: conv2 for one target slot per block (blocks 0..nt-1) ----
    if (bid < nt) {
        int slot = bid;
        int tgv;
        if (slot == 0)      tgv = load_idx(curr, 0, is64);
        else if (slot == 1) tgv = load_idx(dest, 0, is64);
        else                tgv = load_idx(nbr, slot - 2, is64);

        if (tid < Hd) sA[tid] = 0.f;
        __syncthreads();

        int count = g_ne2;
        if (count > MAXE) count = MAXE;
        for (int idx = tid; idx < count * 16; idx += 512) {
            int ent = idx >> 4;
            if (g_e2slot[ent] != slot) continue;
            int l = idx & 15;
            int s   = g_e2src[ent];
            float a = g_e2a[ent];
            float4 xv = *((const float4*)(g_h1 + (size_t)s * Hd) + l);
            float4 wv = __ldg((const float4*)We2 + l);
            float4 bv = __ldg((const float4*)be2 + l);
            float* base2 = &sA[l * 4];
            atomicAdd(base2 + 0, fmaxf(xv.x + fmaf(a, wv.x, bv.x), 0.f));
            atomicAdd(base2 + 1, fmaxf(xv.y + fmaf(a, wv.y, bv.y), 0.f));
            atomicAdd(base2 + 2, fmaxf(xv.z + fmaf(a, wv.z, bv.z), 0.f));
            atomicAdd(base2 + 3, fmaxf(xv.w + fmaf(a, wv.w, bv.w), 0.f));
        }
        __syncthreads();

        if (tid < Hd) sA[tid] += g_h1[(size_t)tgv * Hd + tid];
        __syncthreads();

        // mlp2A: 8 threads per output, split-K shfl reduce
        {
            int j   = tid >> 3;
            int sub = tid & 7;
            float acc = 0.f;
            #pragma unroll
            for (int q = 0; q < 8; q++) {
                int k = sub * 8 + q;
                acc = fmaf(sA[k], __ldg(&W2a[k * Hd + j]), acc);
            }
            acc += __shfl_down_sync(0xffffffffu, acc, 4, 8);
            acc += __shfl_down_sync(0xffffffffu, acc, 2, 8);
            acc += __shfl_down_sync(0xffffffffu, acc, 1, 8);
            if (sub == 0) sU[j] = fmaxf(acc + __ldg(&b2a[j]), 0.f);
        }
        __syncthreads();

        // mlp2B (no relu), write h2 row to global
        {
            int j   = tid >> 3;
            int sub = tid & 7;
            float acc = 0.f;
            #pragma unroll
            for (int q = 0; q < 8; q++) {
                int k = sub * 8 + q;
                acc = fmaf(sU[k], __ldg(&W2b[k * Hd + j]), acc);
            }
            acc += __shfl_down_sync(0xffffffffu, acc, 4, 8);
            acc += __shfl_down_sync(0xffffffffu, acc, 2, 8);
            acc += __shfl_down_sync(0xffffffffu, acc, 1, 8);
            if (sub == 0) g_h2[slot * Hd + j] = acc + __ldg(&b2b[j]);
        }
    }

    grid_barrier();   // all h2 rows written

    // ---- phase 3a: cleanup on block K (concurrent with head blocks) ----
    if (bid == K) {
        for (int i = tid; i < ns1; i += 512) g_bitmap[g_s1[i] >> 5] = 0u;
        if (tid == 0) { g_ns1 = 0; g_ne2 = 0; }
        return;
    }
    if (bid >= K) return;

    // ---- phase 3b: Q head, one neighbor per block (blocks 0..K-1) ----
    {
        int k = bid;
        // sC = [h2_curr(64) | h2_dest(64) | h2_nbr_k(64)]
        if (tid < 2 * Hd) sC[tid] = g_h2[tid];
        else if (tid < 3 * Hd) sC[tid] = g_h2[(2 + k) * Hd + (tid - 2 * Hd)];
        __syncthreads();

        // lin1: 192-deep, 8 threads per output (depth 24), shfl reduce
        {
            int j   = tid >> 3;
            int sub = tid & 7;
            float acc = 0.f;
            #pragma unroll
            for (int q = 0; q < 24; q++) {
                int t = sub * 24 + q;
                acc = fmaf(sC[t], __ldg(&Wl1[t * Hd + j]), acc);
            }
            acc += __shfl_down_sync(0xffffffffu, acc, 4, 8);
            acc += __shfl_down_sync(0xffffffffu, acc, 2, 8);
            acc += __shfl_down_sync(0xffffffffu, acc, 1, 8);
            if (sub == 0) sZ[j] = fmaxf(acc + __ldg(&bl1[j]), 0.f);
        }
        __syncthreads();

        // lin2: warp 0 does the 64-dot via shuffle
        if (tid < 32) {
            float v = fmaf(sZ[tid], __ldg(&Wl2[tid]), 0.f)
                    + sZ[tid + 32] * __ldg(&Wl2[tid + 32]);
            #pragma unroll
            for (int o = 16; o > 0; o >>= 1)
                v += __shfl_down_sync(0xffffffffu, v, o);
            if (tid == 0) out[k] = v + __ldg(&bl2[0]);
        }
    }
}

// ---------------- launcher ----------------
extern "C" void kernel_launch(void* const* d_in, const int* in_sizes, int n_in,
                              void* d_out, int out_size) {
    const float* x    = (const float*)d_in[0];
    const void*  ei   = d_in[1];
    const void*  curr = d_in[2];
    const void*  dest = d_in[3];
    const void*  nbr  = d_in[4];
    const float* ea   = (const float*)d_in[5];
    const float* We1  = (const float*)d_in[6];
    const float* be1  = (const float*)d_in[7];
    const float* W1a  = (const float*)d_in[8];
    const float* b1a  = (const float*)d_in[9];
    const float* W1b  = (const float*)d_in[10];
    const float* b1b  = (const float*)d_in[11];
    const float* We2  = (const float*)d_in[12];
    const float* be2  = (const float*)d_in[13];
    const float* W2a  = (const float*)d_in[14];
    const float* b2a  = (const float*)d_in[15];
    const float* W2b  = (const float*)d_in[16];
    const float* b2b  = (const float*)d_in[17];
    const float* Wl1  = (const float*)d_in[18];
    const float* bl1  = (const float*)d_in[19];
    const float* Wl2  = (const float*)d_in[20];
    const float* bl2  = (const float*)d_in[21];

    int N = in_sizes[0] / Hd;
    int E = in_sizes[5];
    int K = in_sizes[4];
    if (K > MAXK) K = MAXK;

    int scan_blocks = (E + 1023) / 1024;   // 782 for E=800k; co-resident (<=1184)

    k_scanAB<<<scan_blocks, 256>>>(x, ei, ea, curr, dest, nbr, We1, be1,
                                   E, (long long)N, K);
    k_mlpfinal<<<160, 512>>>(x, W1a, b1a, W1b, b1b, We2, be2,
                             curr, dest, nbr, W2a, b2a, W2b, b2b,
                             Wl1, bl1, Wl2, bl2, (float*)d_out, K);
}